// round 2
// baseline (speedup 1.0000x reference)
#include <cuda_runtime.h>
#include <math.h>

// Problem constants
#define NB    8
#define C     528
#define T     16
#define HH    32
#define WW    32
#define R     1024
#define OUTB  8
#define SR    2
#define SCALE (1.0f/16.0f)

// NHWC feature scratch: [b][y][x][c]
__device__ float g_feat[NB * HH * WW * C];

// ---------------------------------------------------------------------------
// Kernel 1: temporal mean + NCHW -> NHWC transpose (coalesced both ways)
// grid: (NB*HH, ceil(C/32)), block: (32, 32)
//   load phase:  tx = x position, ty = channel-in-chunk  (coalesced over x)
//   store phase: tx = channel-in-chunk, ty = x position  (coalesced over c)
// ---------------------------------------------------------------------------
__global__ void mean_t_transpose_kernel(const float* __restrict__ x)
{
    __shared__ float tile[32][33];

    const int by = blockIdx.x;          // b*32 + y
    const int b  = by >> 5;
    const int y  = by & 31;
    const int cchunk = blockIdx.y;

    const int tx = threadIdx.x;
    const int ty = threadIdx.y;

    // load: channel = cchunk*32 + ty, x position = tx
    const int c = cchunk * 32 + ty;
    if (c < C) {
        // x[(((b*C + c)*T + t)*HH + y)*WW + xpos]
        const float* p = x + (((size_t)(b * C + c) * T) * HH + y) * WW + tx;
        float s = 0.f;
        #pragma unroll
        for (int t = 0; t < T; t++)
            s += p[(size_t)t * (HH * WW)];
        tile[ty][tx] = s * (1.0f / T);
    }
    __syncthreads();

    // store: channel = cchunk*32 + tx, x position = ty
    const int c2 = cchunk * 32 + tx;
    if (c2 < C) {
        g_feat[(((size_t)(b * HH + y)) * WW + ty) * C + c2] = tile[tx][ty];
    }
}

// ---------------------------------------------------------------------------
// Kernel 2: fused ROI-align (separable weights) + MLP + sigmoid
// grid: R/4 blocks, block: 544 threads (4 rois per block)
// ---------------------------------------------------------------------------
#define ROIS_PER_BLK 4

__global__ __launch_bounds__(544)
void roi_mlp_kernel(const float* __restrict__ bbox,
                    const float* __restrict__ W1, const float* __restrict__ b1,
                    const float* __restrict__ W2, const float* __restrict__ b2,
                    const float* __restrict__ W3, const float* __restrict__ b3,
                    float* __restrict__ out)
{
    __shared__ float sAx[ROIS_PER_BLK][32];
    __shared__ float sAy[ROIS_PER_BLK][32];
    __shared__ float sPooled[ROIS_PER_BLK][C];
    __shared__ float sH1[ROIS_PER_BLK][128];
    __shared__ float sH2[ROIS_PER_BLK][32];
    __shared__ int   sB[ROIS_PER_BLK];
    __shared__ int   sXlo[ROIS_PER_BLK], sXhi[ROIS_PER_BLK];
    __shared__ int   sYlo[ROIS_PER_BLK], sYhi[ROIS_PER_BLK];

    const int tid = threadIdx.x;
    const int roi0 = blockIdx.x * ROIS_PER_BLK;

    // zero axis weight arrays
    if (tid < ROIS_PER_BLK * 32) {
        sAx[tid >> 5][tid & 31] = 0.f;
        sAy[tid >> 5][tid & 31] = 0.f;
    }
    __syncthreads();

    // build separable weights: 128 threads = 4 rois x 32 samples
    // s in [0,16): x-axis sample s; s in [16,32): y-axis sample s-16
    if (tid < ROIS_PER_BLK * 32) {
        const int r = tid >> 5;
        const int s = tid & 31;
        const int roi = roi0 + r;
        const float* bb = bbox + roi * 5;
        if (s == 0) sB[r] = (int)bb[0];

        const bool is_y = (s >= 16);
        const int  idx  = s & 15;
        const float lo_c = (is_y ? bb[2] : bb[1]) * SCALE - 0.5f;
        const float hi_c = (is_y ? bb[4] : bb[3]) * SCALE - 0.5f;
        const float bin  = (hi_c - lo_c) * (1.0f / OUTB);
        const float v    = lo_c + ((float)idx + 0.5f) * (bin * (1.0f / SR));

        const bool valid = (v >= -1.0f) && (v <= 32.0f);
        float vc = fminf(fmaxf(v, 0.0f), 31.0f);
        float lof = floorf(vc);
        float frac = vc - lof;
        int ilo = (int)lof;
        int ihi = min(ilo + 1, 31);
        if (valid) {
            float* A = is_y ? sAy[r] : sAx[r];
            atomicAdd(&A[ilo], 1.0f - frac);
            atomicAdd(&A[ihi], frac);
        }
    }
    __syncthreads();

    // find support bounds (8 threads: 4 x-axis, 4 y-axis)
    if (tid < 2 * ROIS_PER_BLK) {
        const int r = tid & (ROIS_PER_BLK - 1);
        const bool is_y = (tid >= ROIS_PER_BLK);
        const float* A = is_y ? sAy[r] : sAx[r];
        int lo = 32, hi = -1;
        #pragma unroll
        for (int i = 0; i < 32; i++) {
            if (A[i] != 0.f) { if (i < lo) lo = i; hi = i; }
        }
        if (hi < 0) { lo = 1; hi = 0; }  // empty => skip loops
        if (is_y) { sYlo[r] = lo; sYhi[r] = hi; }
        else      { sXlo[r] = lo; sXhi[r] = hi; }
    }
    __syncthreads();

    // sampling: one thread per channel; separable accumulation
    if (tid < C) {
        const int c = tid;
        #pragma unroll
        for (int r = 0; r < ROIS_PER_BLK; r++) {
            const int b = sB[r];
            const int xlo = sXlo[r], xhi = sXhi[r];
            const int ylo = sYlo[r], yhi = sYhi[r];
            float acc = 0.f;
            for (int y = ylo; y <= yhi; y++) {
                const float ay = sAy[r][y];
                if (ay == 0.f) continue;
                const float* row = g_feat + (((size_t)(b * HH + y)) * WW) * C + c;
                float rs = 0.f;
                for (int xp = xlo; xp <= xhi; xp++) {
                    const float ax = sAx[r][xp];
                    rs += ax * row[(size_t)xp * C];
                }
                acc += ay * rs;
            }
            sPooled[r][c] = acc * (1.0f / 256.0f);
        }
    }
    __syncthreads();

    // MLP layer 1: 512 threads = 4 rois x 128 outputs, relu
    if (tid < ROIS_PER_BLK * 128) {
        const int j = tid & 127;
        const int r = tid >> 7;
        float acc = b1[j];
        const float* p = sPooled[r];
        #pragma unroll 4
        for (int c = 0; c < C; c++)
            acc = fmaf(p[c], W1[c * 128 + j], acc);
        sH1[r][j] = fmaxf(acc, 0.f);
    }
    __syncthreads();

    // MLP layer 2: 128 threads = 4 rois x 32 outputs (no relu)
    if (tid < ROIS_PER_BLK * 32) {
        const int j = tid & 31;
        const int r = tid >> 5;
        float acc = b2[j];
        const float* h = sH1[r];
        #pragma unroll
        for (int k = 0; k < 128; k++)
            acc = fmaf(h[k], W2[k * 32 + j], acc);
        sH2[r][j] = acc;
    }
    __syncthreads();

    // MLP layer 3 + sigmoid: 4 threads
    if (tid < ROIS_PER_BLK) {
        const int r = tid;
        float acc = b3[0];
        #pragma unroll
        for (int k = 0; k < 32; k++)
            acc = fmaf(sH2[r][k], W3[k], acc);
        out[roi0 + r] = 1.0f / (1.0f + expf(-acc));
    }
}

// ---------------------------------------------------------------------------
extern "C" void kernel_launch(void* const* d_in, const int* in_sizes, int n_in,
                              void* d_out, int out_size)
{
    const float* x    = (const float*)d_in[0];
    const float* bbox = (const float*)d_in[1];
    const float* W1   = (const float*)d_in[2];
    const float* b1   = (const float*)d_in[3];
    const float* W2   = (const float*)d_in[4];
    const float* b2   = (const float*)d_in[5];
    const float* W3   = (const float*)d_in[6];
    const float* b3   = (const float*)d_in[7];
    float* out = (float*)d_out;

    dim3 g1(NB * HH, (C + 31) / 32);
    dim3 t1(32, 32);
    mean_t_transpose_kernel<<<g1, t1>>>(x);

    roi_mlp_kernel<<<R / ROIS_PER_BLK, 544>>>(bbox, W1, b1, W2, b2, W3, b3, out);
}

// round 3
// speedup vs baseline: 1.1871x; 1.1871x over previous
#include <cuda_runtime.h>
#include <math.h>

// Problem constants
#define NB    8
#define C     528
#define T     16
#define HH    32
#define WW    32
#define R     1024
#define OUTB  8
#define SR    2
#define SCALE (1.0f/16.0f)

// NHWC feature scratch: [b][y][x][c]
__device__ float g_feat[NB * HH * WW * C];
// pooled scratch: [roi][c]
__device__ float g_pooled[R * C];

// ---------------------------------------------------------------------------
// Kernel 1: temporal mean + NCHW -> NHWC transpose (coalesced both ways)
// grid: (NB*HH, C/32 rounded up), block: (32, 32)
// ---------------------------------------------------------------------------
__global__ void mean_t_transpose_kernel(const float* __restrict__ x)
{
    __shared__ float tile[32][33];

    const int by = blockIdx.x;          // b*32 + y
    const int b  = by >> 5;
    const int y  = by & 31;
    const int cchunk = blockIdx.y;

    const int tx = threadIdx.x;
    const int ty = threadIdx.y;

    const int c = cchunk * 32 + ty;
    if (c < C) {
        const float* p = x + (((size_t)(b * C + c) * T) * HH + y) * WW + tx;
        float s = 0.f;
        #pragma unroll
        for (int t = 0; t < T; t++)
            s += p[(size_t)t * (HH * WW)];
        tile[ty][tx] = s * (1.0f / T);
    }
    __syncthreads();

    const int c2 = cchunk * 32 + tx;
    if (c2 < C) {
        g_feat[(((size_t)(b * HH + y)) * WW + ty) * C + c2] = tile[tx][ty];
    }
}

// ---------------------------------------------------------------------------
// Kernel 2: ROI-align with separable axis weights. One roi per block.
// grid: R, block: 528 threads (one per channel)
// ---------------------------------------------------------------------------
__global__ __launch_bounds__(C)
void roi_align_kernel(const float* __restrict__ bbox)
{
    __shared__ float sAx[32];
    __shared__ float sAy[32];
    __shared__ int   sB;
    __shared__ int   sXlo, sXhi, sYlo, sYhi;

    const int tid = threadIdx.x;
    const int roi = blockIdx.x;

    if (tid < 32)            sAx[tid]      = 0.f;
    else if (tid < 64)       sAy[tid - 32] = 0.f;
    __syncthreads();

    // one thread per axis builds all 16 sample weights serially (deterministic)
    if (tid < 2) {
        const float* bb = bbox + roi * 5;
        if (tid == 0) sB = (int)bb[0];
        float* A = tid ? sAy : sAx;
        const float lo_c = bb[1 + tid] * SCALE - 0.5f;
        const float hi_c = bb[3 + tid] * SCALE - 0.5f;
        const float step = (hi_c - lo_c) * (1.0f / (OUTB * SR));
        int lo = 32, hi = -1;
        #pragma unroll
        for (int s = 0; s < 16; s++) {
            const float v = lo_c + ((float)s + 0.5f) * step;
            const bool valid = (v >= -1.0f) && (v <= 32.0f);
            float vc   = fminf(fmaxf(v, 0.0f), 31.0f);
            float lof  = floorf(vc);
            float frac = vc - lof;
            int ilo = (int)lof;
            int ihi = min(ilo + 1, 31);
            if (valid) {
                A[ilo] += 1.0f - frac;
                A[ihi] += frac;
                lo = min(lo, ilo);
                hi = max(hi, ihi);
            }
        }
        if (hi < 0) { lo = 1; hi = 0; }
        if (tid) { sYlo = lo; sYhi = hi; }
        else     { sXlo = lo; sXhi = hi; }
    }
    __syncthreads();

    if (tid < C) {
        const int b   = sB;
        const int xlo = sXlo, xhi = sXhi;
        const int ylo = sYlo, yhi = sYhi;
        float acc = 0.f;
        for (int y = ylo; y <= yhi; y++) {
            const float ay = sAy[y];
            const float* row = g_feat + (((size_t)(b * HH + y)) * WW) * C + tid;
            float rs = 0.f;
            for (int xp = xlo; xp <= xhi; xp++)
                rs = fmaf(sAx[xp], row[(size_t)xp * C], rs);
            acc = fmaf(ay, rs, acc);
        }
        g_pooled[(size_t)roi * C + tid] = acc * (1.0f / 256.0f);
    }
}

// ---------------------------------------------------------------------------
// Kernel 3: MLP 528 -> 128 (relu) -> 32 -> 1 (sigmoid). 4 rois per block.
// grid: R/4, block: 512
// ---------------------------------------------------------------------------
#define MLP_ROIS 4

__global__ __launch_bounds__(512)
void mlp_kernel(const float* __restrict__ W1, const float* __restrict__ b1,
                const float* __restrict__ W2, const float* __restrict__ b2,
                const float* __restrict__ W3, const float* __restrict__ b3,
                float* __restrict__ out)
{
    __shared__ float sp[MLP_ROIS * C];       // pooled tile
    __shared__ float sH1[MLP_ROIS * 128];
    __shared__ float sH2[MLP_ROIS][32];

    const int tid  = threadIdx.x;
    const int roi0 = blockIdx.x * MLP_ROIS;

    // coalesced copy of 4 consecutive pooled rows
    const float* src = g_pooled + (size_t)roi0 * C;
    #pragma unroll
    for (int i = tid; i < MLP_ROIS * C; i += 512)
        sp[i] = src[i];
    __syncthreads();

    // Layer 1: one (roi, j) output per thread, 4 independent accumulators
    {
        const int r = tid >> 7;          // 0..3
        const int j = tid & 127;
        const float* p = sp + r * C;
        float a0 = 0.f, a1 = 0.f, a2 = 0.f, a3 = 0.f;
        #pragma unroll 4
        for (int c = 0; c < C; c += 4) {
            a0 = fmaf(p[c + 0], W1[(c + 0) * 128 + j], a0);
            a1 = fmaf(p[c + 1], W1[(c + 1) * 128 + j], a1);
            a2 = fmaf(p[c + 2], W1[(c + 2) * 128 + j], a2);
            a3 = fmaf(p[c + 3], W1[(c + 3) * 128 + j], a3);
        }
        float acc = (a0 + a1) + (a2 + a3) + b1[j];
        sH1[r * 128 + j] = fmaxf(acc, 0.f);
    }
    __syncthreads();

    // Layer 2: 4 rois x 32 outputs = 128 threads
    if (tid < MLP_ROIS * 32) {
        const int r = tid >> 5;
        const int j = tid & 31;
        const float* h = sH1 + r * 128;
        float a0 = 0.f, a1 = 0.f, a2 = 0.f, a3 = 0.f;
        #pragma unroll
        for (int k = 0; k < 128; k += 4) {
            a0 = fmaf(h[k + 0], W2[(k + 0) * 32 + j], a0);
            a1 = fmaf(h[k + 1], W2[(k + 1) * 32 + j], a1);
            a2 = fmaf(h[k + 2], W2[(k + 2) * 32 + j], a2);
            a3 = fmaf(h[k + 3], W2[(k + 3) * 32 + j], a3);
        }
        sH2[r][j] = (a0 + a1) + (a2 + a3) + b2[j];
    }
    __syncthreads();

    // Layer 3 + sigmoid: one warp per roi, butterfly reduce
    if (tid < MLP_ROIS * 32) {
        const int r    = tid >> 5;
        const int lane = tid & 31;
        float v = sH2[r][lane] * W3[lane];
        #pragma unroll
        for (int off = 16; off > 0; off >>= 1)
            v += __shfl_xor_sync(0xFFFFFFFF, v, off);
        if (lane == 0)
            out[roi0 + r] = 1.0f / (1.0f + expf(-(v + b3[0])));
    }
}

// ---------------------------------------------------------------------------
extern "C" void kernel_launch(void* const* d_in, const int* in_sizes, int n_in,
                              void* d_out, int out_size)
{
    const float* x    = (const float*)d_in[0];
    const float* bbox = (const float*)d_in[1];
    const float* W1   = (const float*)d_in[2];
    const float* b1   = (const float*)d_in[3];
    const float* W2   = (const float*)d_in[4];
    const float* b2   = (const float*)d_in[5];
    const float* W3   = (const float*)d_in[6];
    const float* b3   = (const float*)d_in[7];
    float* out = (float*)d_out;

    dim3 g1(NB * HH, (C + 31) / 32);
    dim3 t1(32, 32);
    mean_t_transpose_kernel<<<g1, t1>>>(x);

    roi_align_kernel<<<R, C>>>(bbox);

    mlp_kernel<<<R / MLP_ROIS, 512>>>(W1, b1, W2, b2, W3, b3, out);
}

// round 5
// speedup vs baseline: 1.4283x; 1.2032x over previous
#include <cuda_runtime.h>
#include <math.h>

// Problem constants
#define NB    8
#define C     528
#define T     16
#define HH    32
#define WW    32
#define R     1024
#define OUTB  8
#define SR    2
#define SCALE (1.0f/16.0f)

// NHWC feature scratch: [b][y][x][c]
__device__ float g_feat[NB * HH * WW * C];

// ---------------------------------------------------------------------------
// Kernel 1: temporal mean + NCHW -> NHWC transpose (coalesced both ways)
// grid: (NB*HH, C/32 rounded up), block: (32, 32)
// x is streamed (read-once) -> __ldcs to keep feat L2-resident for kernel 2.
// ---------------------------------------------------------------------------
__global__ void mean_t_transpose_kernel(const float* __restrict__ x)
{
    __shared__ float tile[32][33];

    const int by = blockIdx.x;          // b*32 + y
    const int b  = by >> 5;
    const int y  = by & 31;
    const int cchunk = blockIdx.y;

    const int tx = threadIdx.x;
    const int ty = threadIdx.y;

    const int c = cchunk * 32 + ty;
    if (c < C) {
        const float* p = x + (((size_t)(b * C + c) * T) * HH + y) * WW + tx;
        float s0 = 0.f, s1 = 0.f;
        #pragma unroll
        for (int t = 0; t < T; t += 2) {
            s0 += __ldcs(p + (size_t)t       * (HH * WW));
            s1 += __ldcs(p + (size_t)(t + 1) * (HH * WW));
        }
        tile[ty][tx] = (s0 + s1) * (1.0f / T);
    }
    __syncthreads();

    const int c2 = cchunk * 32 + tx;
    if (c2 < C) {
        g_feat[(((size_t)(b * HH + y)) * WW + ty) * C + c2] = tile[tx][ty];
    }
}

// ---------------------------------------------------------------------------
// Kernel 2: fused ROI-align (separable weights) + MLP + sigmoid.
// One roi per block. grid: R, block: 512.
// ---------------------------------------------------------------------------
__global__ __launch_bounds__(512)
void roi_mlp_fused_kernel(const float* __restrict__ bbox,
                          const float* __restrict__ W1, const float* __restrict__ b1,
                          const float* __restrict__ W2, const float* __restrict__ b2,
                          const float* __restrict__ W3, const float* __restrict__ b3,
                          float* __restrict__ out)
{
    __shared__ float sAx[32];
    __shared__ float sAy[32];
    __shared__ int   sB;
    __shared__ int   sXlo, sXhi, sYlo, sYhi;
    __shared__ float sPooled[C];
    __shared__ float sPart1[4][128];
    __shared__ float sH1[128];
    __shared__ float sPart2[4][32];
    __shared__ float sH2[32];

    const int tid = threadIdx.x;
    const int roi = blockIdx.x;

    if (tid < 32)       sAx[tid]      = 0.f;
    else if (tid < 64)  sAy[tid - 32] = 0.f;
    __syncthreads();

    // Phase A: per-axis separable weights (2 threads, deterministic serial)
    if (tid < 2) {
        const float* bb = bbox + roi * 5;
        if (tid == 0) sB = (int)bb[0];
        float* A = tid ? sAy : sAx;
        const float lo_c = bb[1 + tid] * SCALE - 0.5f;
        const float hi_c = bb[3 + tid] * SCALE - 0.5f;
        const float step = (hi_c - lo_c) * (1.0f / (OUTB * SR));
        int lo = 32, hi = -1;
        #pragma unroll
        for (int s = 0; s < 16; s++) {
            const float v = lo_c + ((float)s + 0.5f) * step;
            const bool valid = (v >= -1.0f) && (v <= 32.0f);
            float vc   = fminf(fmaxf(v, 0.0f), 31.0f);
            float lof  = floorf(vc);
            float frac = vc - lof;
            int ilo = (int)lof;
            int ihi = min(ilo + 1, 31);
            if (valid) {
                A[ilo] += 1.0f - frac;
                A[ihi] += frac;
                lo = min(lo, ilo);
                hi = max(hi, ihi);
            }
        }
        if (hi < 0) { lo = 1; hi = 0; }
        if (tid) { sYlo = lo; sYhi = hi; }
        else     { sXlo = lo; sXhi = hi; }
    }
    __syncthreads();

    // Phase B: pooled[c] = (1/256) * sum_y Ay[y] * sum_x Ax[x] * feat[b,y,x,c]
    {
        const int b   = sB;
        const int xlo = sXlo, xhi = sXhi;
        const int ylo = sYlo, yhi = sYhi;
        for (int c = tid; c < C; c += 512) {
            float acc = 0.f;
            for (int y = ylo; y <= yhi; y++) {
                const float ay = sAy[y];
                const float* row = g_feat + (((size_t)(b * HH + y)) * WW) * C + c;
                float rs = 0.f;
                for (int xp = xlo; xp <= xhi; xp++)
                    rs = fmaf(sAx[xp], row[(size_t)xp * C], rs);
                acc = fmaf(ay, rs, acc);
            }
            sPooled[c] = acc * (1.0f / 256.0f);
        }
    }
    __syncthreads();

    // Phase C: layer 1 (528 -> 128, relu). 512 threads = 128 outputs x 4 c-parts.
    {
        const int part = tid >> 7;        // 0..3, 132 channels each
        const int j    = tid & 127;
        const int c0 = part * 132;
        float a0 = 0.f, a1 = 0.f;
        #pragma unroll 2
        for (int c = c0; c < c0 + 132; c += 2) {
            a0 = fmaf(sPooled[c],     W1[(c)     * 128 + j], a0);
            a1 = fmaf(sPooled[c + 1], W1[(c + 1) * 128 + j], a1);
        }
        sPart1[part][j] = a0 + a1;
    }
    __syncthreads();
    if (tid < 128) {
        float acc = (sPart1[0][tid] + sPart1[1][tid])
                  + (sPart1[2][tid] + sPart1[3][tid]) + b1[tid];
        sH1[tid] = fmaxf(acc, 0.f);
    }
    __syncthreads();

    // Phase D: layer 2 (128 -> 32). 128 threads = 32 outputs x 4 k-parts.
    if (tid < 128) {
        const int part = tid >> 5;        // 0..3, 32 k each
        const int j    = tid & 31;
        const int k0 = part * 32;
        float a0 = 0.f, a1 = 0.f;
        #pragma unroll
        for (int k = k0; k < k0 + 32; k += 2) {
            a0 = fmaf(sH1[k],     W2[(k)     * 32 + j], a0);
            a1 = fmaf(sH1[k + 1], W2[(k + 1) * 32 + j], a1);
        }
        sPart2[part][j] = a0 + a1;
    }
    __syncthreads();
    if (tid < 32) {
        sH2[tid] = (sPart2[0][tid] + sPart2[1][tid])
                 + (sPart2[2][tid] + sPart2[3][tid]) + b2[tid];
    }
    __syncthreads();

    // Phase E: layer 3 + sigmoid (one warp, butterfly reduce)
    if (tid < 32) {
        float v = sH2[tid] * W3[tid];
        #pragma unroll
        for (int off = 16; off > 0; off >>= 1)
            v += __shfl_xor_sync(0xFFFFFFFF, v, off);
        if (tid == 0)
            out[roi] = 1.0f / (1.0f + expf(-(v + b3[0])));
    }
}

// ---------------------------------------------------------------------------
extern "C" void kernel_launch(void* const* d_in, const int* in_sizes, int n_in,
                              void* d_out, int out_size)
{
    const float* x    = (const float*)d_in[0];
    const float* bbox = (const float*)d_in[1];
    const float* W1   = (const float*)d_in[2];
    const float* b1   = (const float*)d_in[3];
    const float* W2   = (const float*)d_in[4];
    const float* b2   = (const float*)d_in[5];
    const float* W3   = (const float*)d_in[6];
    const float* b3   = (const float*)d_in[7];
    float* out = (float*)d_out;

    dim3 g1(NB * HH, (C + 31) / 32);
    dim3 t1(32, 32);
    mean_t_transpose_kernel<<<g1, t1>>>(x);

    roi_mlp_fused_kernel<<<R, 512>>>(bbox, W1, b1, W2, b2, W3, b3, out);
}